// round 2
// baseline (speedup 1.0000x reference)
#include <cuda_runtime.h>

#define MDIM 4096
#define CDIM 256   // HEADS*OUT_F
#define NHEADS 4
#define WPR 128    // bitmask words per row (4096/32)

// ---------------- device scratch (no allocations allowed) ----------------
__device__ float    g_Wh[MDIM * CDIM];
__device__ float    g_x [MDIM * CDIM];
__device__ float    g_t3[MDIM * 64];
__device__ float    g_src[MDIM * NHEADS];
__device__ float    g_dst[MDIM * NHEADS];
__device__ float    g_dmax[NHEADS];
__device__ unsigned g_Abits[MDIM * WPR];

// ---------------- adjacency -> bitmask pack (once per launch) ----------------
__global__ void pack_kernel(const int* __restrict__ A) {
    int idx = blockIdx.x * 256 + threadIdx.x;        // over 16.7M elements
    unsigned b = __ballot_sync(0xffffffffu, A[idx] == 1);
    if ((idx & 31) == 0) g_Abits[idx >> 5] = b;
}

// ---------------- generic GEMM: C[M][N] = A[M][K] @ W[N][K]^T + bias ----
// BM=BN=64, BK=16, 256 threads, 4x4 micro-tile per thread.
__global__ void gemm_kernel(const float* __restrict__ A, const float* __restrict__ W,
                            const float* __restrict__ bias, float* __restrict__ C,
                            int M, int N, int K) {
    __shared__ float As[16][68];
    __shared__ float Ws[16][68];
    const int tid = threadIdx.x;
    const int tx = tid & 15, ty = tid >> 4;
    const int i0 = blockIdx.y * 64, n0 = blockIdx.x * 64;
    const int lr = tid >> 2, lk = (tid & 3) * 4;

    float acc[4][4] = {};
    for (int k0 = 0; k0 < K; k0 += 16) {
        float4 av = *(const float4*)(A + (size_t)(i0 + lr) * K + k0 + lk);
        As[lk + 0][lr] = av.x; As[lk + 1][lr] = av.y;
        As[lk + 2][lr] = av.z; As[lk + 3][lr] = av.w;
        float4 wv = make_float4(0.f, 0.f, 0.f, 0.f);
        if (n0 + lr < N) wv = *(const float4*)(W + (size_t)(n0 + lr) * K + k0 + lk);
        Ws[lk + 0][lr] = wv.x; Ws[lk + 1][lr] = wv.y;
        Ws[lk + 2][lr] = wv.z; Ws[lk + 3][lr] = wv.w;
        __syncthreads();
#pragma unroll
        for (int kk = 0; kk < 16; kk++) {
            float4 a4 = *(const float4*)&As[kk][ty * 4];
            float4 w4 = *(const float4*)&Ws[kk][tx * 4];
            acc[0][0] += a4.x * w4.x; acc[0][1] += a4.x * w4.y; acc[0][2] += a4.x * w4.z; acc[0][3] += a4.x * w4.w;
            acc[1][0] += a4.y * w4.x; acc[1][1] += a4.y * w4.y; acc[1][2] += a4.y * w4.z; acc[1][3] += a4.y * w4.w;
            acc[2][0] += a4.z * w4.x; acc[2][1] += a4.z * w4.y; acc[2][2] += a4.z * w4.z; acc[2][3] += a4.z * w4.w;
            acc[3][0] += a4.w * w4.x; acc[3][1] += a4.w * w4.y; acc[3][2] += a4.w * w4.z; acc[3][3] += a4.w * w4.w;
        }
        __syncthreads();
    }
#pragma unroll
    for (int u = 0; u < 4; u++) {
        int row = i0 + ty * 4 + u;
#pragma unroll
        for (int v = 0; v < 4; v++) {
            int col = n0 + tx * 4 + v;
            if (col < N) C[(size_t)row * N + col] = acc[u][v] + bias[col];
        }
    }
}

// ---------------- src/dst scores ----------------
__global__ void srcdst_kernel(const float* __restrict__ Wh, const float* __restrict__ a) {
    int idx = blockIdx.x * blockDim.x + threadIdx.x;   // 16384 threads
    int m = idx >> 2, h = idx & 3;
    const float4* w  = (const float4*)(Wh + (size_t)m * CDIM + h * 64);
    const float4* as = (const float4*)(a + h * 128);
    const float4* ad = (const float4*)(a + h * 128 + 64);
    float s = 0.f, d = 0.f;
#pragma unroll
    for (int q = 0; q < 16; q++) {
        float4 wv = w[q], av = as[q], dv = ad[q];
        s += wv.x * av.x + wv.y * av.y + wv.z * av.z + wv.w * av.w;
        d += wv.x * dv.x + wv.y * dv.y + wv.z * dv.z + wv.w * dv.w;
    }
    g_src[idx] = s;
    g_dst[idx] = d;
}

// ---------------- per-head global max of dst ----------------
__global__ void dmax_kernel() {
    int h = blockIdx.x;
    __shared__ float s[256];
    float m = -3.4e38f;
    for (int j = threadIdx.x; j < MDIM; j += 256) m = fmaxf(m, g_dst[j * 4 + h]);
    s[threadIdx.x] = m;
    __syncthreads();
    for (int st = 128; st > 0; st >>= 1) {
        if (threadIdx.x < st) s[threadIdx.x] = fmaxf(s[threadIdx.x], s[threadIdx.x + st]);
        __syncthreads();
    }
    if (threadIdx.x == 0) g_dmax[h] = s[0];
}

// ---------------- fused masked-softmax attention ----------------
// CTA: 32 rows; loop over j in 32-tiles.
// Phase A (ALL 256 threads): each thread pair owns one (row,head); each half
// computes 16 masked exp scores into smem, Z combined via shfl at the end.
// Phase B (256 threads): 4 cols x 8 rows each, probs @ Wh accumulation.
#define ATTN_SMEM ((32 * 256 + 32 * 128 + 128 + 128) * 4 + 32 * 4)

__global__ void attn_kernel(const float* __restrict__ Wh, float* __restrict__ xout) {
    extern __shared__ float smem[];
    float* wh_sh  = smem;                       // 32 x 256
    float* e_sh   = smem + 32 * 256;            // 32 x 128  [jj][h*32+ii]
    float* dst_sh = e_sh + 32 * 128;            // 32 x 4
    float* zf     = dst_sh + 128;               // 128
    unsigned* abits = (unsigned*)(zf + 128);    // 32

    const int tid = threadIdx.x;
    const int i0 = blockIdx.x * 32;
    const int og = tid & 63;        // output float4-group: cols og*4..og*4+3
    const int grp = tid >> 6;       // row group (8 rows)
    const int h = og >> 4;          // head of output columns
    // phase-A identity: thread pair (2t,2t+1) owns task t = (ahh,aii)
    const int task = tid >> 1, half = tid & 1;
    const int aii = task & 31, ahh = task >> 5;
    const int lrow = tid >> 3, lf = tid & 7;    // wh tile load mapping

    float4 acc[8];
#pragma unroll
    for (int r = 0; r < 8; r++) acc[r] = make_float4(0.f, 0.f, 0.f, 0.f);

    float z = 0.f;
    float srcv = g_src[(i0 + aii) * 4 + ahh];
    float tmax = srcv + g_dmax[ahh];
    float Mi = tmax > 0.f ? tmax : 0.01f * tmax;

    const float4* Wh4 = (const float4*)Wh;

    for (int jt = 0; jt < MDIM / 32; jt++) {
        const int j0 = jt * 32;
        __syncthreads();   // previous phase B done; safe to overwrite tiles
        // load Wh tile (32 rows x 256 cols)
#pragma unroll
        for (int k2 = 0; k2 < 8; k2++) {
            float4 v = Wh4[(size_t)(j0 + lrow) * 64 + lf + 8 * k2];
            ((float4*)(wh_sh + lrow * 256))[lf + 8 * k2] = v;
        }
        if (tid < 128) dst_sh[tid] = g_dst[(j0 + (tid >> 2)) * 4 + (tid & 3)];
        if (tid < 32) abits[tid] = g_Abits[(size_t)(i0 + tid) * WPR + jt];
        __syncthreads();
        // phase A: scores -> e_sh, Z accumulate (16 j per thread)
        {
            unsigned bits = abits[aii] >> (half * 16);
#pragma unroll
            for (int q = 0; q < 16; q++) {
                int jj = half * 16 + q;
                float s = srcv + dst_sh[jj * 4 + ahh];
                s = (s > 0.f ? s : 0.01f * s) - Mi;
                float e = ((bits >> q) & 1u) ? __expf(s) : 0.f;
                e_sh[jj * 128 + ahh * 32 + aii] = e;
                z += e;
            }
        }
        __syncthreads();
        // phase B: acc += e * Wh
#pragma unroll 4
        for (int jj = 0; jj < 32; jj++) {
            float4 w = ((const float4*)(wh_sh + jj * 256))[og];
            const float* ep = e_sh + jj * 128 + h * 32 + grp * 8;
            float4 e0 = *(const float4*)(ep);
            float4 e1 = *(const float4*)(ep + 4);
            acc[0].x += e0.x * w.x; acc[0].y += e0.x * w.y; acc[0].z += e0.x * w.z; acc[0].w += e0.x * w.w;
            acc[1].x += e0.y * w.x; acc[1].y += e0.y * w.y; acc[1].z += e0.y * w.z; acc[1].w += e0.y * w.w;
            acc[2].x += e0.z * w.x; acc[2].y += e0.z * w.y; acc[2].z += e0.z * w.z; acc[2].w += e0.z * w.w;
            acc[3].x += e0.w * w.x; acc[3].y += e0.w * w.y; acc[3].z += e0.w * w.z; acc[3].w += e0.w * w.w;
            acc[4].x += e1.x * w.x; acc[4].y += e1.x * w.y; acc[4].z += e1.x * w.z; acc[4].w += e1.x * w.w;
            acc[5].x += e1.y * w.x; acc[5].y += e1.y * w.y; acc[5].z += e1.y * w.z; acc[5].w += e1.y * w.w;
            acc[6].x += e1.z * w.x; acc[6].y += e1.z * w.y; acc[6].z += e1.z * w.z; acc[6].w += e1.z * w.w;
            acc[7].x += e1.w * w.x; acc[7].y += e1.w * w.y; acc[7].z += e1.w * w.z; acc[7].w += e1.w * w.w;
        }
    }
    // combine Z across the thread pair and publish
    z += __shfl_xor_sync(0xffffffffu, z, 1);
    __syncthreads();
    if (half == 0) zf[task] = z;   // task == ahh*32 + aii
    __syncthreads();
#pragma unroll
    for (int r = 0; r < 8; r++) {
        int i = grp * 8 + r;
        float inv = 1.0f / zf[h * 32 + i];
        float4 v = acc[r];
        v.x *= inv; v.y *= inv; v.z *= inv; v.w *= inv;
        ((float4*)xout)[(size_t)(i0 + i) * 64 + og] = v;
    }
}

// ---------------- launch ----------------
extern "C" void kernel_launch(void* const* d_in, const int* in_sizes, int n_in,
                              void* d_out, int out_size) {
    const float* h    = (const float*)d_in[0];
    const int*   A    = (const int*)  d_in[1];
    const float* W1_w = (const float*)d_in[2];
    const float* W1_b = (const float*)d_in[3];
    const float* a1   = (const float*)d_in[4];
    const float* W3_w = (const float*)d_in[5];
    const float* W3_b = (const float*)d_in[6];
    const float* W2_w = (const float*)d_in[7];
    const float* W2_b = (const float*)d_in[8];
    const float* a2   = (const float*)d_in[9];
    const float* FL_w = (const float*)d_in[10];
    const float* FL_b = (const float*)d_in[11];

    float* out_x   = (float*)d_out;                         // x: (1,4096,256)
    float* out_cls = out_x + (size_t)MDIM * CDIM;           // out: (1,4096,40)

    void* p;
    cudaGetSymbolAddress(&p, g_Wh); float* Wh = (float*)p;
    cudaGetSymbolAddress(&p, g_x);  float* x1 = (float*)p;
    cudaGetSymbolAddress(&p, g_t3); float* t3 = (float*)p;

    cudaFuncSetAttribute(attn_kernel, cudaFuncAttributeMaxDynamicSharedMemorySize, ATTN_SMEM);

    // adjacency bitmask (A constant across the launch; deterministic)
    pack_kernel<<<(MDIM * MDIM) / 256, 256>>>(A);

    // block 1
    gemm_kernel<<<dim3(4, 64), 256>>>(h, W1_w, W1_b, Wh, MDIM, 256, 512);
    srcdst_kernel<<<64, 256>>>(Wh, a1);
    dmax_kernel<<<4, 256>>>();
    attn_kernel<<<128, 256, ATTN_SMEM>>>(Wh, x1);
    // middle projection
    gemm_kernel<<<dim3(1, 64), 256>>>(x1, W3_w, W3_b, t3, MDIM, 64, 256);
    // block 2
    gemm_kernel<<<dim3(4, 64), 256>>>(t3, W2_w, W2_b, Wh, MDIM, 256, 64);
    srcdst_kernel<<<64, 256>>>(Wh, a2);
    dmax_kernel<<<4, 256>>>();
    attn_kernel<<<128, 256, ATTN_SMEM>>>(Wh, out_x);
    // classifier head
    gemm_kernel<<<dim3(1, 64), 256>>>(out_x, FL_w, FL_b, out_cls, MDIM, 40, 256);
}

// round 3
// speedup vs baseline: 1.0119x; 1.0119x over previous
#include <cuda_runtime.h>

#define MDIM 4096
#define CDIM 256   // HEADS*OUT_F
#define NHEADS 4
#define WPR 128    // bitmask words per row (4096/32)

// ---------------- device scratch (no allocations allowed) ----------------
__device__ float    g_Wh[MDIM * CDIM];
__device__ float    g_x [MDIM * CDIM];
__device__ float    g_t3[MDIM * 64];
__device__ float    g_src[MDIM * NHEADS];
__device__ float    g_dst[MDIM * NHEADS];
__device__ unsigned g_dmax_u[2][NHEADS];
__device__ unsigned g_Abits[MDIM * WPR];

// ---------------- packed f32x2 helpers (FFMA2: 2 lane-FMAs / instruction) ----
__device__ __forceinline__ void ffma2(unsigned long long& acc, unsigned long long a,
                                      unsigned long long b) {
    asm("fma.rn.f32x2 %0, %1, %2, %0;" : "+l"(acc) : "l"(a), "l"(b));
}
__device__ __forceinline__ unsigned long long pack2(float x, float y) {
    unsigned long long r;
    asm("mov.b64 %0, {%1, %2};" : "=l"(r) : "f"(x), "f"(y));
    return r;
}
__device__ __forceinline__ float2 unpack2(unsigned long long v) {
    float2 f;
    asm("mov.b64 {%0, %1}, %2;" : "=f"(f.x), "=f"(f.y) : "l"(v));
    return f;
}

// monotone float<->uint key for atomicMax over signed floats
__device__ __forceinline__ unsigned fkey(float f) {
    unsigned b = __float_as_uint(f);
    return (b & 0x80000000u) ? ~b : (b | 0x80000000u);
}
__device__ __forceinline__ float fdec(unsigned k) {
    return (k & 0x80000000u) ? __uint_as_float(k & 0x7fffffffu) : __uint_as_float(~k);
}

// ---------------- adjacency -> bitmask pack (also zeroes dmax keys) ----------
__global__ void pack_kernel(const int* __restrict__ A) {
    int idx = blockIdx.x * 256 + threadIdx.x;        // over 16.7M elements
    if (blockIdx.x == 0 && threadIdx.x < 2 * NHEADS)
        ((unsigned*)g_dmax_u)[threadIdx.x] = 0;      // below every real key
    unsigned b = __ballot_sync(0xffffffffu, A[idx] == 1);
    if ((idx & 31) == 0) g_Abits[idx >> 5] = b;
}

// ---------------- generic GEMM: C[M][N] = A[M][K] @ W[N][K]^T + bias ----
// BM=BN=64, BK=16, 256 threads, 4x4 micro-tile per thread, FFMA2 inner.
__global__ void gemm_kernel(const float* __restrict__ A, const float* __restrict__ W,
                            const float* __restrict__ bias, float* __restrict__ C,
                            int M, int N, int K) {
    __shared__ float As[16][68];
    __shared__ float Ws[16][68];
    const int tid = threadIdx.x;
    const int tx = tid & 15, ty = tid >> 4;
    const int i0 = blockIdx.y * 64, n0 = blockIdx.x * 64;
    const int lr = tid >> 2, lk = (tid & 3) * 4;

    unsigned long long acc2[4][2] = {};   // [row u][col pair], zero == {0.f,0.f}
    for (int k0 = 0; k0 < K; k0 += 16) {
        float4 av = *(const float4*)(A + (size_t)(i0 + lr) * K + k0 + lk);
        As[lk + 0][lr] = av.x; As[lk + 1][lr] = av.y;
        As[lk + 2][lr] = av.z; As[lk + 3][lr] = av.w;
        float4 wv = make_float4(0.f, 0.f, 0.f, 0.f);
        if (n0 + lr < N) wv = *(const float4*)(W + (size_t)(n0 + lr) * K + k0 + lk);
        Ws[lk + 0][lr] = wv.x; Ws[lk + 1][lr] = wv.y;
        Ws[lk + 2][lr] = wv.z; Ws[lk + 3][lr] = wv.w;
        __syncthreads();
#pragma unroll
        for (int kk = 0; kk < 16; kk++) {
            float4 a4 = *(const float4*)&As[kk][ty * 4];
            float4 w4 = *(const float4*)&Ws[kk][tx * 4];
            unsigned long long wp0 = pack2(w4.x, w4.y);
            unsigned long long wp1 = pack2(w4.z, w4.w);
            unsigned long long aa;
            aa = pack2(a4.x, a4.x); ffma2(acc2[0][0], aa, wp0); ffma2(acc2[0][1], aa, wp1);
            aa = pack2(a4.y, a4.y); ffma2(acc2[1][0], aa, wp0); ffma2(acc2[1][1], aa, wp1);
            aa = pack2(a4.z, a4.z); ffma2(acc2[2][0], aa, wp0); ffma2(acc2[2][1], aa, wp1);
            aa = pack2(a4.w, a4.w); ffma2(acc2[3][0], aa, wp0); ffma2(acc2[3][1], aa, wp1);
        }
        __syncthreads();
    }
#pragma unroll
    for (int u = 0; u < 4; u++) {
        int row = i0 + ty * 4 + u;
        float2 p0 = unpack2(acc2[u][0]);
        float2 p1 = unpack2(acc2[u][1]);
        float vals[4] = {p0.x, p0.y, p1.x, p1.y};
#pragma unroll
        for (int v = 0; v < 4; v++) {
            int col = n0 + tx * 4 + v;
            if (col < N) C[(size_t)row * N + col] = vals[v] + bias[col];
        }
    }
}

// ---------------- src/dst scores + fused per-head dst max ----------------
__global__ void srcdst_kernel(const float* __restrict__ Wh, const float* __restrict__ a,
                              unsigned* __restrict__ dmax_u) {
    int idx = blockIdx.x * blockDim.x + threadIdx.x;   // 16384 threads
    int m = idx >> 2, h = idx & 3;
    const float4* w  = (const float4*)(Wh + (size_t)m * CDIM + h * 64);
    const float4* as = (const float4*)(a + h * 128);
    const float4* ad = (const float4*)(a + h * 128 + 64);
    float s = 0.f, d = 0.f;
#pragma unroll
    for (int q = 0; q < 16; q++) {
        float4 wv = w[q], av = as[q], dv = ad[q];
        s += wv.x * av.x + wv.y * av.y + wv.z * av.z + wv.w * av.w;
        d += wv.x * dv.x + wv.y * dv.y + wv.z * dv.z + wv.w * dv.w;
    }
    g_src[idx] = s;
    g_dst[idx] = d;
    // per-warp, per-head max of d (same-h lanes are stride-4 apart)
    float mx = d;
    mx = fmaxf(mx, __shfl_xor_sync(0xffffffffu, mx, 4));
    mx = fmaxf(mx, __shfl_xor_sync(0xffffffffu, mx, 8));
    mx = fmaxf(mx, __shfl_xor_sync(0xffffffffu, mx, 16));
    if ((threadIdx.x & 31) < 4) atomicMax(&dmax_u[threadIdx.x & 3], fkey(mx));
}

// ---------------- fused masked-softmax attention ----------------
// CTA: 32 rows; loop over j in 32-tiles.
// Phase A (256 threads): thread pair per (row,head), 16 masked exp each.
// Phase B (256 threads): 4 cols x 8 rows each via packed FFMA2 (row pairs).
#define ATTN_SMEM ((32 * 256 + 32 * 128 + 128 + 128) * 4 + 32 * 4)

__global__ void attn_kernel(const float* __restrict__ Wh,
                            const unsigned* __restrict__ dmax_u,
                            float* __restrict__ xout) {
    extern __shared__ float smem[];
    float* wh_sh  = smem;                       // 32 x 256
    float* e_sh   = smem + 32 * 256;            // 32 x 128  [jj][h*32+ii]
    float* dst_sh = e_sh + 32 * 128;            // 32 x 4
    float* zf     = dst_sh + 128;               // 128
    unsigned* abits = (unsigned*)(zf + 128);    // 32

    const int tid = threadIdx.x;
    const int i0 = blockIdx.x * 32;
    const int og = tid & 63;        // output float4-group: cols og*4..og*4+3
    const int grp = tid >> 6;       // row group (8 rows)
    const int h = og >> 4;          // head of output columns
    const int task = tid >> 1, half = tid & 1;  // phase-A pair identity
    const int aii = task & 31, ahh = task >> 5;
    const int lrow = tid >> 3, lf = tid & 7;    // wh tile load mapping

    unsigned long long acc2[4][4] = {};  // [col c][row pair rp]

    float z = 0.f;
    float srcv = g_src[(i0 + aii) * 4 + ahh];
    float tmax = srcv + fdec(dmax_u[ahh]);
    float Mi = tmax > 0.f ? tmax : 0.01f * tmax;

    const float4* Wh4 = (const float4*)Wh;

    for (int jt = 0; jt < MDIM / 32; jt++) {
        const int j0 = jt * 32;
        __syncthreads();   // previous phase B done; safe to overwrite tiles
#pragma unroll
        for (int k2 = 0; k2 < 8; k2++) {
            float4 v = Wh4[(size_t)(j0 + lrow) * 64 + lf + 8 * k2];
            ((float4*)(wh_sh + lrow * 256))[lf + 8 * k2] = v;
        }
        if (tid < 128) dst_sh[tid] = g_dst[(j0 + (tid >> 2)) * 4 + (tid & 3)];
        if (tid < 32) abits[tid] = g_Abits[(size_t)(i0 + tid) * WPR + jt];
        __syncthreads();
        // phase A: 16 masked exp scores per thread
        {
            unsigned bits = abits[aii] >> (half * 16);
#pragma unroll
            for (int q = 0; q < 16; q++) {
                int jj = half * 16 + q;
                float s = srcv + dst_sh[jj * 4 + ahh];
                s = (s > 0.f ? s : 0.01f * s) - Mi;
                float e = ((bits >> q) & 1u) ? __expf(s) : 0.f;
                e_sh[jj * 128 + ahh * 32 + aii] = e;
                z += e;
            }
        }
        __syncthreads();
        // phase B: acc += e * Wh via packed FFMA2
#pragma unroll 4
        for (int jj = 0; jj < 32; jj++) {
            float4 w = ((const float4*)(wh_sh + jj * 256))[og];
            const ulonglong2* ep = (const ulonglong2*)(e_sh + jj * 128 + h * 32 + grp * 8);
            ulonglong2 ea = ep[0];
            ulonglong2 eb = ep[1];
            unsigned long long ww;
            ww = pack2(w.x, w.x);
            ffma2(acc2[0][0], ww, ea.x); ffma2(acc2[0][1], ww, ea.y);
            ffma2(acc2[0][2], ww, eb.x); ffma2(acc2[0][3], ww, eb.y);
            ww = pack2(w.y, w.y);
            ffma2(acc2[1][0], ww, ea.x); ffma2(acc2[1][1], ww, ea.y);
            ffma2(acc2[1][2], ww, eb.x); ffma2(acc2[1][3], ww, eb.y);
            ww = pack2(w.z, w.z);
            ffma2(acc2[2][0], ww, ea.x); ffma2(acc2[2][1], ww, ea.y);
            ffma2(acc2[2][2], ww, eb.x); ffma2(acc2[2][3], ww, eb.y);
            ww = pack2(w.w, w.w);
            ffma2(acc2[3][0], ww, ea.x); ffma2(acc2[3][1], ww, ea.y);
            ffma2(acc2[3][2], ww, eb.x); ffma2(acc2[3][3], ww, eb.y);
        }
    }
    // combine Z across the thread pair and publish
    z += __shfl_xor_sync(0xffffffffu, z, 1);
    __syncthreads();
    if (half == 0) zf[task] = z;   // task == ahh*32 + aii
    __syncthreads();
#pragma unroll
    for (int rp = 0; rp < 4; rp++) {
        int r0 = grp * 8 + 2 * rp, r1 = r0 + 1;
        float2 c0 = unpack2(acc2[0][rp]);
        float2 c1 = unpack2(acc2[1][rp]);
        float2 c2 = unpack2(acc2[2][rp]);
        float2 c3 = unpack2(acc2[3][rp]);
        float inv0 = 1.0f / zf[h * 32 + r0];
        float inv1 = 1.0f / zf[h * 32 + r1];
        float4 v0 = make_float4(c0.x * inv0, c1.x * inv0, c2.x * inv0, c3.x * inv0);
        float4 v1 = make_float4(c0.y * inv1, c1.y * inv1, c2.y * inv1, c3.y * inv1);
        ((float4*)xout)[(size_t)(i0 + r0) * 64 + og] = v0;
        ((float4*)xout)[(size_t)(i0 + r1) * 64 + og] = v1;
    }
}

// ---------------- launch ----------------
extern "C" void kernel_launch(void* const* d_in, const int* in_sizes, int n_in,
                              void* d_out, int out_size) {
    const float* h    = (const float*)d_in[0];
    const int*   A    = (const int*)  d_in[1];
    const float* W1_w = (const float*)d_in[2];
    const float* W1_b = (const float*)d_in[3];
    const float* a1   = (const float*)d_in[4];
    const float* W3_w = (const float*)d_in[5];
    const float* W3_b = (const float*)d_in[6];
    const float* W2_w = (const float*)d_in[7];
    const float* W2_b = (const float*)d_in[8];
    const float* a2   = (const float*)d_in[9];
    const float* FL_w = (const float*)d_in[10];
    const float* FL_b = (const float*)d_in[11];

    float* out_x   = (float*)d_out;                         // x: (1,4096,256)
    float* out_cls = out_x + (size_t)MDIM * CDIM;           // out: (1,4096,40)

    void* p;
    cudaGetSymbolAddress(&p, g_Wh); float* Wh = (float*)p;
    cudaGetSymbolAddress(&p, g_x);  float* x1 = (float*)p;
    cudaGetSymbolAddress(&p, g_t3); float* t3 = (float*)p;
    cudaGetSymbolAddress(&p, g_dmax_u); unsigned* dmax0 = (unsigned*)p;
    unsigned* dmax1 = dmax0 + NHEADS;

    cudaFuncSetAttribute(attn_kernel, cudaFuncAttributeMaxDynamicSharedMemorySize, ATTN_SMEM);

    // adjacency bitmask + dmax-key zeroing (A constant; deterministic)
    pack_kernel<<<(MDIM * MDIM) / 256, 256>>>(A);

    // block 1
    gemm_kernel<<<dim3(4, 64), 256>>>(h, W1_w, W1_b, Wh, MDIM, 256, 512);
    srcdst_kernel<<<64, 256>>>(Wh, a1, dmax0);
    attn_kernel<<<128, 256, ATTN_SMEM>>>(Wh, dmax0, x1);
    // middle projection
    gemm_kernel<<<dim3(1, 64), 256>>>(x1, W3_w, W3_b, t3, MDIM, 64, 256);
    // block 2
    gemm_kernel<<<dim3(4, 64), 256>>>(t3, W2_w, W2_b, Wh, MDIM, 256, 64);
    srcdst_kernel<<<64, 256>>>(Wh, a2, dmax1);
    attn_kernel<<<128, 256, ATTN_SMEM>>>(Wh, dmax1, out_x);
    // classifier head
    gemm_kernel<<<dim3(1, 64), 256>>>(out_x, FL_w, FL_b, out_cls, MDIM, 40, 256);
}

// round 4
// speedup vs baseline: 1.4430x; 1.4261x over previous
#include <cuda_runtime.h>

#define MDIM 4096
#define CDIM 256   // HEADS*OUT_F
#define NHEADS 4
#define WPR 128    // bitmask words per row (4096/32)
#define SPLITS 4   // j-range splits for attn (occupancy)

// ---------------- device scratch (no allocations allowed) ----------------
__device__ float    g_Wh[MDIM * CDIM];
__device__ float    g_x [MDIM * CDIM];
__device__ float    g_t3[MDIM * 64];
__device__ float    g_src[MDIM * NHEADS];
__device__ float    g_dst[MDIM * NHEADS];
__device__ unsigned g_dmax_u[2][NHEADS];
__device__ unsigned g_Abits[MDIM * WPR];
__device__ float    g_pacc[SPLITS][MDIM * CDIM];   // un-normalized partial outputs
__device__ float    g_pz  [SPLITS][MDIM * NHEADS]; // partial softmax denominators

// ---------------- packed f32x2 helpers (FFMA2) ----------------
__device__ __forceinline__ void ffma2(unsigned long long& acc, unsigned long long a,
                                      unsigned long long b) {
    asm("fma.rn.f32x2 %0, %1, %2, %0;" : "+l"(acc) : "l"(a), "l"(b));
}
__device__ __forceinline__ unsigned long long pack2(float x, float y) {
    unsigned long long r;
    asm("mov.b64 %0, {%1, %2};" : "=l"(r) : "f"(x), "f"(y));
    return r;
}
__device__ __forceinline__ float2 unpack2(unsigned long long v) {
    float2 f;
    asm("mov.b64 {%0, %1}, %2;" : "=f"(f.x), "=f"(f.y) : "l"(v));
    return f;
}

// monotone float<->uint key for atomicMax over signed floats
__device__ __forceinline__ unsigned fkey(float f) {
    unsigned b = __float_as_uint(f);
    return (b & 0x80000000u) ? ~b : (b | 0x80000000u);
}
__device__ __forceinline__ float fdec(unsigned k) {
    return (k & 0x80000000u) ? __uint_as_float(k & 0x7fffffffu) : __uint_as_float(~k);
}

// ---------------- adjacency -> bitmask pack (also zeroes dmax keys) ----------
__global__ void pack_kernel(const int* __restrict__ A) {
    int idx = blockIdx.x * 256 + threadIdx.x;        // over 16.7M elements
    if (blockIdx.x == 0 && threadIdx.x < 2 * NHEADS)
        ((unsigned*)g_dmax_u)[threadIdx.x] = 0;      // below every real key
    unsigned b = __ballot_sync(0xffffffffu, A[idx] == 1);
    if ((idx & 31) == 0) g_Abits[idx >> 5] = b;
}

// ---------------- generic GEMM: C[M][N] = A[M][K] @ W[N][K]^T + bias ----
__global__ void gemm_kernel(const float* __restrict__ A, const float* __restrict__ W,
                            const float* __restrict__ bias, float* __restrict__ C,
                            int M, int N, int K) {
    __shared__ float As[16][68];
    __shared__ float Ws[16][68];
    const int tid = threadIdx.x;
    const int tx = tid & 15, ty = tid >> 4;
    const int i0 = blockIdx.y * 64, n0 = blockIdx.x * 64;
    const int lr = tid >> 2, lk = (tid & 3) * 4;

    unsigned long long acc2[4][2] = {};
    for (int k0 = 0; k0 < K; k0 += 16) {
        float4 av = *(const float4*)(A + (size_t)(i0 + lr) * K + k0 + lk);
        As[lk + 0][lr] = av.x; As[lk + 1][lr] = av.y;
        As[lk + 2][lr] = av.z; As[lk + 3][lr] = av.w;
        float4 wv = make_float4(0.f, 0.f, 0.f, 0.f);
        if (n0 + lr < N) wv = *(const float4*)(W + (size_t)(n0 + lr) * K + k0 + lk);
        Ws[lk + 0][lr] = wv.x; Ws[lk + 1][lr] = wv.y;
        Ws[lk + 2][lr] = wv.z; Ws[lk + 3][lr] = wv.w;
        __syncthreads();
#pragma unroll
        for (int kk = 0; kk < 16; kk++) {
            float4 a4 = *(const float4*)&As[kk][ty * 4];
            float4 w4 = *(const float4*)&Ws[kk][tx * 4];
            unsigned long long wp0 = pack2(w4.x, w4.y);
            unsigned long long wp1 = pack2(w4.z, w4.w);
            unsigned long long aa;
            aa = pack2(a4.x, a4.x); ffma2(acc2[0][0], aa, wp0); ffma2(acc2[0][1], aa, wp1);
            aa = pack2(a4.y, a4.y); ffma2(acc2[1][0], aa, wp0); ffma2(acc2[1][1], aa, wp1);
            aa = pack2(a4.z, a4.z); ffma2(acc2[2][0], aa, wp0); ffma2(acc2[2][1], aa, wp1);
            aa = pack2(a4.w, a4.w); ffma2(acc2[3][0], aa, wp0); ffma2(acc2[3][1], aa, wp1);
        }
        __syncthreads();
    }
#pragma unroll
    for (int u = 0; u < 4; u++) {
        int row = i0 + ty * 4 + u;
        float2 p0 = unpack2(acc2[u][0]);
        float2 p1 = unpack2(acc2[u][1]);
        float vals[4] = {p0.x, p0.y, p1.x, p1.y};
#pragma unroll
        for (int v = 0; v < 4; v++) {
            int col = n0 + tx * 4 + v;
            if (col < N) C[(size_t)row * N + col] = vals[v] + bias[col];
        }
    }
}

// ---------------- src/dst scores + fused per-head dst max ----------------
__global__ void srcdst_kernel(const float* __restrict__ Wh, const float* __restrict__ a,
                              unsigned* __restrict__ dmax_u) {
    int idx = blockIdx.x * blockDim.x + threadIdx.x;   // 16384 threads
    int m = idx >> 2, h = idx & 3;
    const float4* w  = (const float4*)(Wh + (size_t)m * CDIM + h * 64);
    const float4* as = (const float4*)(a + h * 128);
    const float4* ad = (const float4*)(a + h * 128 + 64);
    float s = 0.f, d = 0.f;
#pragma unroll
    for (int q = 0; q < 16; q++) {
        float4 wv = w[q], av = as[q], dv = ad[q];
        s += wv.x * av.x + wv.y * av.y + wv.z * av.z + wv.w * av.w;
        d += wv.x * dv.x + wv.y * dv.y + wv.z * dv.z + wv.w * dv.w;
    }
    g_src[idx] = s;
    g_dst[idx] = d;
    float mx = d;
    mx = fmaxf(mx, __shfl_xor_sync(0xffffffffu, mx, 4));
    mx = fmaxf(mx, __shfl_xor_sync(0xffffffffu, mx, 8));
    mx = fmaxf(mx, __shfl_xor_sync(0xffffffffu, mx, 16));
    if ((threadIdx.x & 31) < 4) atomicMax(&dmax_u[threadIdx.x & 3], fkey(mx));
}

// ---------------- fused masked-softmax attention, split over j ----------------
// blockIdx.x: row tile (32 rows). blockIdx.y: j-split (MDIM/32/SPLITS tiles each).
// Phase A (256 threads): thread pair per (row,head), 16 masked exp each.
// Phase B (256 threads): 4 cols x 8 rows via packed FFMA2.
// Writes UN-normalized partial acc + partial Z to per-split buffers.
#define ATTN_SMEM ((32 * 256 + 32 * 128 + 128) * 4 + 32 * 4)
#define TILES_PER_SPLIT (MDIM / 32 / SPLITS)

__global__ __launch_bounds__(256, 3)
void attn_kernel(const float* __restrict__ Wh, const unsigned* __restrict__ dmax_u) {
    extern __shared__ float smem[];
    float* wh_sh  = smem;                       // 32 x 256
    float* e_sh   = smem + 32 * 256;            // 32 x 128  [jj][h*32+ii]
    float* dst_sh = e_sh + 32 * 128;            // 32 x 4
    unsigned* abits = (unsigned*)(dst_sh + 128);// 32

    const int tid = threadIdx.x;
    const int i0 = blockIdx.x * 32;
    const int sp = blockIdx.y;
    const int og = tid & 63;
    const int grp = tid >> 6;
    const int h = og >> 4;
    const int task = tid >> 1, half = tid & 1;
    const int aii = task & 31, ahh = task >> 5;
    const int lrow = tid >> 3, lf = tid & 7;

    unsigned long long acc2[4][4] = {};  // [col c][row pair rp]

    float z = 0.f;
    float srcv = g_src[(i0 + aii) * 4 + ahh];
    float tmax = srcv + fdec(dmax_u[ahh]);
    float Mi = tmax > 0.f ? tmax : 0.01f * tmax;

    const float4* Wh4 = (const float4*)Wh;

    for (int jt = sp * TILES_PER_SPLIT; jt < (sp + 1) * TILES_PER_SPLIT; jt++) {
        const int j0 = jt * 32;
        __syncthreads();
#pragma unroll
        for (int k2 = 0; k2 < 8; k2++) {
            float4 v = Wh4[(size_t)(j0 + lrow) * 64 + lf + 8 * k2];
            ((float4*)(wh_sh + lrow * 256))[lf + 8 * k2] = v;
        }
        if (tid < 128) dst_sh[tid] = g_dst[(j0 + (tid >> 2)) * 4 + (tid & 3)];
        if (tid < 32) abits[tid] = g_Abits[(size_t)(i0 + tid) * WPR + jt];
        __syncthreads();
        // phase A: 16 masked exp scores per thread
        {
            unsigned bits = abits[aii] >> (half * 16);
#pragma unroll
            for (int q = 0; q < 16; q++) {
                int jj = half * 16 + q;
                float s = srcv + dst_sh[jj * 4 + ahh];
                s = (s > 0.f ? s : 0.01f * s) - Mi;
                float e = ((bits >> q) & 1u) ? __expf(s) : 0.f;
                e_sh[jj * 128 + ahh * 32 + aii] = e;
                z += e;
            }
        }
        __syncthreads();
        // phase B: acc += e * Wh via packed FFMA2
#pragma unroll 4
        for (int jj = 0; jj < 32; jj++) {
            float4 w = ((const float4*)(wh_sh + jj * 256))[og];
            const ulonglong2* ep = (const ulonglong2*)(e_sh + jj * 128 + h * 32 + grp * 8);
            ulonglong2 ea = ep[0];
            ulonglong2 eb = ep[1];
            unsigned long long ww;
            ww = pack2(w.x, w.x);
            ffma2(acc2[0][0], ww, ea.x); ffma2(acc2[0][1], ww, ea.y);
            ffma2(acc2[0][2], ww, eb.x); ffma2(acc2[0][3], ww, eb.y);
            ww = pack2(w.y, w.y);
            ffma2(acc2[1][0], ww, ea.x); ffma2(acc2[1][1], ww, ea.y);
            ffma2(acc2[1][2], ww, eb.x); ffma2(acc2[1][3], ww, eb.y);
            ww = pack2(w.z, w.z);
            ffma2(acc2[2][0], ww, ea.x); ffma2(acc2[2][1], ww, ea.y);
            ffma2(acc2[2][2], ww, eb.x); ffma2(acc2[2][3], ww, eb.y);
            ww = pack2(w.w, w.w);
            ffma2(acc2[3][0], ww, ea.x); ffma2(acc2[3][1], ww, ea.y);
            ffma2(acc2[3][2], ww, eb.x); ffma2(acc2[3][3], ww, eb.y);
        }
    }
    // publish partial Z (pair-combined) and un-normalized partial acc
    z += __shfl_xor_sync(0xffffffffu, z, 1);
    if (half == 0) g_pz[sp][(i0 + aii) * 4 + ahh] = z;
#pragma unroll
    for (int rp = 0; rp < 4; rp++) {
        int r0 = grp * 8 + 2 * rp, r1 = r0 + 1;
        float2 c0 = unpack2(acc2[0][rp]);
        float2 c1 = unpack2(acc2[1][rp]);
        float2 c2 = unpack2(acc2[2][rp]);
        float2 c3 = unpack2(acc2[3][rp]);
        ((float4*)g_pacc[sp])[(size_t)(i0 + r0) * 64 + og] = make_float4(c0.x, c1.x, c2.x, c3.x);
        ((float4*)g_pacc[sp])[(size_t)(i0 + r1) * 64 + og] = make_float4(c0.y, c1.y, c2.y, c3.y);
    }
}

// ---------------- combine split partials: out = sum(acc) / sum(z) ----------
__global__ void reduce_kernel(float* __restrict__ xout) {
    int idx = blockIdx.x * 256 + threadIdx.x;   // over 4096*64 float4 groups
    int i = idx >> 6, og = idx & 63, h = og >> 4;
    float4 s = make_float4(0.f, 0.f, 0.f, 0.f);
    float z = 0.f;
#pragma unroll
    for (int sp = 0; sp < SPLITS; sp++) {
        float4 p = ((const float4*)g_pacc[sp])[idx];
        s.x += p.x; s.y += p.y; s.z += p.z; s.w += p.w;
        z += g_pz[sp][i * 4 + h];
    }
    float inv = 1.0f / z;
    s.x *= inv; s.y *= inv; s.z *= inv; s.w *= inv;
    ((float4*)xout)[idx] = s;
}

// ---------------- launch ----------------
extern "C" void kernel_launch(void* const* d_in, const int* in_sizes, int n_in,
                              void* d_out, int out_size) {
    const float* h    = (const float*)d_in[0];
    const int*   A    = (const int*)  d_in[1];
    const float* W1_w = (const float*)d_in[2];
    const float* W1_b = (const float*)d_in[3];
    const float* a1   = (const float*)d_in[4];
    const float* W3_w = (const float*)d_in[5];
    const float* W3_b = (const float*)d_in[6];
    const float* W2_w = (const float*)d_in[7];
    const float* W2_b = (const float*)d_in[8];
    const float* a2   = (const float*)d_in[9];
    const float* FL_w = (const float*)d_in[10];
    const float* FL_b = (const float*)d_in[11];

    float* out_x   = (float*)d_out;                         // x: (1,4096,256)
    float* out_cls = out_x + (size_t)MDIM * CDIM;           // out: (1,4096,40)

    void* p;
    cudaGetSymbolAddress(&p, g_Wh); float* Wh = (float*)p;
    cudaGetSymbolAddress(&p, g_x);  float* x1 = (float*)p;
    cudaGetSymbolAddress(&p, g_t3); float* t3 = (float*)p;
    cudaGetSymbolAddress(&p, g_dmax_u); unsigned* dmax0 = (unsigned*)p;
    unsigned* dmax1 = dmax0 + NHEADS;

    cudaFuncSetAttribute(attn_kernel, cudaFuncAttributeMaxDynamicSharedMemorySize, ATTN_SMEM);

    pack_kernel<<<(MDIM * MDIM) / 256, 256>>>(A);

    // block 1
    gemm_kernel<<<dim3(4, 64), 256>>>(h, W1_w, W1_b, Wh, MDIM, 256, 512);
    srcdst_kernel<<<64, 256>>>(Wh, a1, dmax0);
    attn_kernel<<<dim3(128, SPLITS), 256, ATTN_SMEM>>>(Wh, dmax0);
    reduce_kernel<<<(MDIM * 64) / 256, 256>>>(x1);
    // middle projection
    gemm_kernel<<<dim3(1, 64), 256>>>(x1, W3_w, W3_b, t3, MDIM, 64, 256);
    // block 2
    gemm_kernel<<<dim3(4, 64), 256>>>(t3, W2_w, W2_b, Wh, MDIM, 256, 64);
    srcdst_kernel<<<64, 256>>>(Wh, a2, dmax1);
    attn_kernel<<<dim3(128, SPLITS), 256, ATTN_SMEM>>>(Wh, dmax1);
    reduce_kernel<<<(MDIM * 64) / 256, 256>>>(out_x);
    // classifier head
    gemm_kernel<<<dim3(1, 64), 256>>>(out_x, FL_w, FL_b, out_cls, MDIM, 40, 256);
}

// round 6
// speedup vs baseline: 1.5764x; 1.0925x over previous
#include <cuda_runtime.h>

#define MDIM 4096
#define CDIM 256   // HEADS*OUT_F
#define NHEADS 4
#define WPR 128    // bitmask words per row (4096/32)
#define SPLITS 4   // j-range splits for attn (occupancy)

// ---------------- device scratch (no allocations allowed) ----------------
__device__ float    g_Wh[MDIM * CDIM];
__device__ float    g_x [MDIM * CDIM];
__device__ float    g_t3[MDIM * 64];
__device__ float    g_src[MDIM * NHEADS];
__device__ float    g_dst[MDIM * NHEADS];
__device__ unsigned g_dmax_u[2][NHEADS];
__device__ unsigned g_Abits[MDIM * WPR];
__device__ float    g_pacc[SPLITS][MDIM * CDIM];   // un-normalized partial outputs
__device__ float    g_pz  [SPLITS][MDIM * NHEADS]; // partial softmax denominators

// ---------------- packed f32x2 helpers (FFMA2) ----------------
__device__ __forceinline__ void ffma2(unsigned long long& acc, unsigned long long a,
                                      unsigned long long b) {
    asm("fma.rn.f32x2 %0, %1, %2, %0;" : "+l"(acc) : "l"(a), "l"(b));
}
__device__ __forceinline__ unsigned long long pack2(float x, float y) {
    unsigned long long r;
    asm("mov.b64 %0, {%1, %2};" : "=l"(r) : "f"(x), "f"(y));
    return r;
}
__device__ __forceinline__ float2 unpack2(unsigned long long v) {
    float2 f;
    asm("mov.b64 {%0, %1}, %2;" : "=f"(f.x), "=f"(f.y) : "l"(v));
    return f;
}

// monotone float<->uint key for atomicMax over signed floats
__device__ __forceinline__ unsigned fkey(float f) {
    unsigned b = __float_as_uint(f);
    return (b & 0x80000000u) ? ~b : (b | 0x80000000u);
}
__device__ __forceinline__ float fdec(unsigned k) {
    return (k & 0x80000000u) ? __uint_as_float(k & 0x7fffffffu) : __uint_as_float(~k);
}

// cp.async 16B: global -> shared without register staging
__device__ __forceinline__ unsigned smem_u32(const void* p) {
    unsigned a;
    asm("{ .reg .u64 t; cvta.to.shared.u64 t, %1; cvt.u32.u64 %0, t; }" : "=r"(a) : "l"(p));
    return a;
}
__device__ __forceinline__ void cp_async16(unsigned saddr, const void* gptr) {
    asm volatile("cp.async.ca.shared.global [%0], [%1], 16;" :: "r"(saddr), "l"(gptr));
}

// ---------------- adjacency -> bitmask pack (also zeroes dmax keys) ----------
__global__ void pack_kernel(const int* __restrict__ A) {
    int idx = blockIdx.x * 256 + threadIdx.x;        // over 16.7M elements
    if (blockIdx.x == 0 && threadIdx.x < 2 * NHEADS)
        ((unsigned*)g_dmax_u)[threadIdx.x] = 0;      // below every real key
    unsigned b = __ballot_sync(0xffffffffu, A[idx] == 1);
    if ((idx & 31) == 0) g_Abits[idx >> 5] = b;
}

// ---------------- generic GEMM: C[M][N] = A[M][K] @ W[N][K]^T + bias ----
__global__ void gemm_kernel(const float* __restrict__ A, const float* __restrict__ W,
                            const float* __restrict__ bias, float* __restrict__ C,
                            int M, int N, int K) {
    __shared__ float As[16][68];
    __shared__ float Ws[16][68];
    const int tid = threadIdx.x;
    const int tx = tid & 15, ty = tid >> 4;
    const int i0 = blockIdx.y * 64, n0 = blockIdx.x * 64;
    const int lr = tid >> 2, lk = (tid & 3) * 4;

    unsigned long long acc2[4][2] = {};
    for (int k0 = 0; k0 < K; k0 += 16) {
        float4 av = *(const float4*)(A + (size_t)(i0 + lr) * K + k0 + lk);
        As[lk + 0][lr] = av.x; As[lk + 1][lr] = av.y;
        As[lk + 2][lr] = av.z; As[lk + 3][lr] = av.w;
        float4 wv = make_float4(0.f, 0.f, 0.f, 0.f);
        if (n0 + lr < N) wv = *(const float4*)(W + (size_t)(n0 + lr) * K + k0 + lk);
        Ws[lk + 0][lr] = wv.x; Ws[lk + 1][lr] = wv.y;
        Ws[lk + 2][lr] = wv.z; Ws[lk + 3][lr] = wv.w;
        __syncthreads();
#pragma unroll
        for (int kk = 0; kk < 16; kk++) {
            float4 a4 = *(const float4*)&As[kk][ty * 4];
            float4 w4 = *(const float4*)&Ws[kk][tx * 4];
            unsigned long long wp0 = pack2(w4.x, w4.y);
            unsigned long long wp1 = pack2(w4.z, w4.w);
            unsigned long long aa;
            aa = pack2(a4.x, a4.x); ffma2(acc2[0][0], aa, wp0); ffma2(acc2[0][1], aa, wp1);
            aa = pack2(a4.y, a4.y); ffma2(acc2[1][0], aa, wp0); ffma2(acc2[1][1], aa, wp1);
            aa = pack2(a4.z, a4.z); ffma2(acc2[2][0], aa, wp0); ffma2(acc2[2][1], aa, wp1);
            aa = pack2(a4.w, a4.w); ffma2(acc2[3][0], aa, wp0); ffma2(acc2[3][1], aa, wp1);
        }
        __syncthreads();
    }
#pragma unroll
    for (int u = 0; u < 4; u++) {
        int row = i0 + ty * 4 + u;
        float2 p0 = unpack2(acc2[u][0]);
        float2 p1 = unpack2(acc2[u][1]);
        float vals[4] = {p0.x, p0.y, p1.x, p1.y};
#pragma unroll
        for (int v = 0; v < 4; v++) {
            int col = n0 + tx * 4 + v;
            if (col < N) C[(size_t)row * N + col] = vals[v] + bias[col];
        }
    }
}

// ---------------- src/dst scores + fused per-head dst max ----------------
__global__ void srcdst_kernel(const float* __restrict__ Wh, const float* __restrict__ a,
                              unsigned* __restrict__ dmax_u) {
    int idx = blockIdx.x * blockDim.x + threadIdx.x;   // 16384 threads
    int m = idx >> 2, h = idx & 3;
    const float4* w  = (const float4*)(Wh + (size_t)m * CDIM + h * 64);
    const float4* as = (const float4*)(a + h * 128);
    const float4* ad = (const float4*)(a + h * 128 + 64);
    float s = 0.f, d = 0.f;
#pragma unroll
    for (int q = 0; q < 16; q++) {
        float4 wv = w[q], av = as[q], dv = ad[q];
        s += wv.x * av.x + wv.y * av.y + wv.z * av.z + wv.w * av.w;
        d += wv.x * dv.x + wv.y * dv.y + wv.z * dv.z + wv.w * dv.w;
    }
    g_src[idx] = s;
    g_dst[idx] = d;
    float mx = d;
    mx = fmaxf(mx, __shfl_xor_sync(0xffffffffu, mx, 4));
    mx = fmaxf(mx, __shfl_xor_sync(0xffffffffu, mx, 8));
    mx = fmaxf(mx, __shfl_xor_sync(0xffffffffu, mx, 16));
    if ((threadIdx.x & 31) < 4) atomicMax(&dmax_u[threadIdx.x & 3], fkey(mx));
}

// ---------------- fused masked-softmax attention, split over j ----------------
// blockIdx.x: row tile (32 rows). blockIdx.y: j-split.
// 4 CTAs/SM -> grid 512 in ONE resident wave.
// Wh tile staged via cp.async so its L2 latency hides under phase A.
#define ATTN_SMEM ((32 * 256 + 32 * 128 + 128) * 4 + 32 * 4)
#define TILES_PER_SPLIT (MDIM / 32 / SPLITS)
#define L2E 1.4426950408889634f

__global__ __launch_bounds__(256, 4)
void attn_kernel(const float* __restrict__ Wh, const unsigned* __restrict__ dmax_u) {
    extern __shared__ float smem[];
    float* wh_sh  = smem;                       // 32 x 256
    float* e_sh   = smem + 32 * 256;            // 32 x 128  [jj][h*32+ii]
    float* dst_sh = e_sh + 32 * 128;            // [h][jj] : 4 x 32 (transposed)
    unsigned* abits = (unsigned*)(dst_sh + 128);// 32

    const int tid = threadIdx.x;
    const int i0 = blockIdx.x * 32;
    const int sp = blockIdx.y;
    const int og = tid & 63;
    const int grp = tid >> 6;
    const int h = og >> 4;
    const int task = tid >> 1, half = tid & 1;
    const int aii = task & 31, ahh = task >> 5;
    const int lrow = tid >> 3, lf = tid & 7;

    unsigned long long acc2[4][4] = {};  // [col c][row pair rp]

    float z = 0.f;
    float srcv = g_src[(i0 + aii) * 4 + ahh];
    float tmax = srcv + fdec(dmax_u[ahh]);
    float Mi = fmaxf(tmax, 0.01f * tmax);
    float nMiL = -Mi * L2E;              // folded into exp2 argument

    const float4* Wh4 = (const float4*)Wh;
    const unsigned wh_sh_base = smem_u32(wh_sh) + (unsigned)(lrow * 256) * 4u;

    for (int jt = sp * TILES_PER_SPLIT; jt < (sp + 1) * TILES_PER_SPLIT; jt++) {
        const int j0 = jt * 32;
        __syncthreads();   // prev phase B done: wh_sh / e_sh reusable
        // async-stage Wh tile (no register staging, latency hides under phase A)
#pragma unroll
        for (int k2 = 0; k2 < 8; k2++)
            cp_async16(wh_sh_base + (unsigned)(lf + 8 * k2) * 16u,
                       Wh4 + (size_t)(j0 + lrow) * 64 + lf + 8 * k2);
        asm volatile("cp.async.commit_group;");
        if (tid < 128) dst_sh[(tid & 3) * 32 + (tid >> 2)] =
            g_dst[(j0 + (tid >> 2)) * 4 + (tid & 3)];
        if (tid < 32) abits[tid] = g_Abits[(size_t)(i0 + tid) * WPR + jt];
        __syncthreads();   // dst_sh / abits visible
        // phase A: 16 masked exp scores per thread (vectorized dst loads)
        {
            unsigned bits = abits[aii] >> (half * 16);
            const float4* dbase = (const float4*)(dst_sh + ahh * 32 + half * 16);
            float* ebase = e_sh + ahh * 32 + aii + half * 16 * 128;
#pragma unroll
            for (int q4 = 0; q4 < 4; q4++) {
                float4 d4 = dbase[q4];
                float dd[4] = {d4.x, d4.y, d4.z, d4.w};
#pragma unroll
                for (int t = 0; t < 4; t++) {
                    int q = q4 * 4 + t;
                    float s = srcv + dd[t];
                    s = fmaxf(s, 0.01f * s);
                    float e = ((bits >> q) & 1u) ? exp2f(fmaf(s, L2E, nMiL)) : 0.f;
                    ebase[q * 128] = e;
                    z += e;
                }
            }
        }
        asm volatile("cp.async.wait_group 0;");
        __syncthreads();   // e_sh + wh_sh visible
        // phase B: acc += e * Wh via packed FFMA2
#pragma unroll 4
        for (int jj = 0; jj < 32; jj++) {
            float4 w = ((const float4*)(wh_sh + jj * 256))[og];
            const ulonglong2* ep = (const ulonglong2*)(e_sh + jj * 128 + h * 32 + grp * 8);
            ulonglong2 ea = ep[0];
            ulonglong2 eb = ep[1];
            unsigned long long ww;
            ww = pack2(w.x, w.x);
            ffma2(acc2[0][0], ww, ea.x); ffma2(acc2[0][1], ww, ea.y);
            ffma2(acc2[0][2], ww, eb.x); ffma2(acc2[0][3], ww, eb.y);
            ww = pack2(w.y, w.y);
            ffma2(acc2[1][0], ww, ea.x); ffma2(acc2[1][1], ww, ea.y);
            ffma2(acc2[1][2], ww, eb.x); ffma2(acc2[1][3], ww, eb.y);
            ww = pack2(w.z, w.z);
            ffma2(acc2[2][0], ww, ea.x); ffma2(acc2[2][1], ww, ea.y);
            ffma2(acc2[2][2], ww, eb.x); ffma2(acc2[2][3], ww, eb.y);
            ww = pack2(w.w, w.w);
            ffma2(acc2[3][0], ww, ea.x); ffma2(acc2[3][1], ww, ea.y);
            ffma2(acc2[3][2], ww, eb.x); ffma2(acc2[3][3], ww, eb.y);
        }
    }
    // publish partial Z (pair-combined) and un-normalized partial acc
    z += __shfl_xor_sync(0xffffffffu, z, 1);
    if (half == 0) g_pz[sp][(i0 + aii) * 4 + ahh] = z;
#pragma unroll
    for (int rp = 0; rp < 4; rp++) {
        int r0 = grp * 8 + 2 * rp, r1 = r0 + 1;
        float2 c0 = unpack2(acc2[0][rp]);
        float2 c1 = unpack2(acc2[1][rp]);
        float2 c2 = unpack2(acc2[2][rp]);
        float2 c3 = unpack2(acc2[3][rp]);
        ((float4*)g_pacc[sp])[(size_t)(i0 + r0) * 64 + og] = make_float4(c0.x, c1.x, c2.x, c3.x);
        ((float4*)g_pacc[sp])[(size_t)(i0 + r1) * 64 + og] = make_float4(c0.y, c1.y, c2.y, c3.y);
    }
}

// ---------------- combine split partials: out = sum(acc) / sum(z) ----------
__global__ void reduce_kernel(float* __restrict__ xout) {
    int idx = blockIdx.x * 256 + threadIdx.x;   // over 4096*64 float4 groups
    int i = idx >> 6, og = idx & 63, h = og >> 4;
    float4 s = make_float4(0.f, 0.f, 0.f, 0.f);
    float z = 0.f;
#pragma unroll
    for (int sp = 0; sp < SPLITS; sp++) {
        float4 p = ((const float4*)g_pacc[sp])[idx];
        s.x += p.x; s.y += p.y; s.z += p.z; s.w += p.w;
        z += g_pz[sp][i * 4 + h];
    }
    float inv = 1.0f / z;
    s.x *= inv; s.y *= inv; s.z *= inv; s.w *= inv;
    ((float4*)xout)[idx] = s;
}

// ---------------- launch ----------------
extern "C" void kernel_launch(void* const* d_in, const int* in_sizes, int n_in,
                              void* d_out, int out_size) {
    const float* h    = (const float*)d_in[0];
    const int*   A    = (const int*)  d_in[1];
    const float* W1_w = (const float*)d_in[2];
    const float* W1_b = (const float*)d_in[3];
    const float* a1   = (const float*)d_in[4];
    const float* W3_w = (const float*)d_in[5];
    const float* W3_b = (const float*)d_in[6];
    const float* W2_w = (const float*)d_in[7];
    const float* W2_b = (const float*)d_in[8];
    const float* a2   = (const float*)d_in[9];
    const float* FL_w = (const float*)d_in[10];
    const float* FL_b = (const float*)d_in[11];

    float* out_x   = (float*)d_out;                         // x: (1,4096,256)
    float* out_cls = out_x + (size_t)MDIM * CDIM;           // out: (1,4096,40)

    void* p;
    cudaGetSymbolAddress(&p, g_Wh); float* Wh = (float*)p;
    cudaGetSymbolAddress(&p, g_x);  float* x1 = (float*)p;
    cudaGetSymbolAddress(&p, g_t3); float* t3 = (float*)p;
    cudaGetSymbolAddress(&p, g_dmax_u); unsigned* dmax0 = (unsigned*)p;
    unsigned* dmax1 = dmax0 + NHEADS;

    cudaFuncSetAttribute(attn_kernel, cudaFuncAttributeMaxDynamicSharedMemorySize, ATTN_SMEM);

    pack_kernel<<<(MDIM * MDIM) / 256, 256>>>(A);

    // block 1
    gemm_kernel<<<dim3(4, 64), 256>>>(h, W1_w, W1_b, Wh, MDIM, 256, 512);
    srcdst_kernel<<<64, 256>>>(Wh, a1, dmax0);
    attn_kernel<<<dim3(128, SPLITS), 256, ATTN_SMEM>>>(Wh, dmax0);
    reduce_kernel<<<(MDIM * 64) / 256, 256>>>(x1);
    // middle projection
    gemm_kernel<<<dim3(1, 64), 256>>>(x1, W3_w, W3_b, t3, MDIM, 64, 256);
    // block 2
    gemm_kernel<<<dim3(4, 64), 256>>>(t3, W2_w, W2_b, Wh, MDIM, 256, 64);
    srcdst_kernel<<<64, 256>>>(Wh, a2, dmax1);
    attn_kernel<<<dim3(128, SPLITS), 256, ATTN_SMEM>>>(Wh, dmax1);
    reduce_kernel<<<(MDIM * 64) / 256, 256>>>(out_x);
    // classifier head
    gemm_kernel<<<dim3(1, 64), 256>>>(out_x, FL_w, FL_b, out_cls, MDIM, 40, 256);
}

// round 8
// speedup vs baseline: 1.6708x; 1.0599x over previous
#include <cuda_runtime.h>

#define MDIM 4096
#define CDIM 256   // HEADS*OUT_F
#define NHEADS 4
#define WPR 128    // bitmask words per row (4096/32)
#define SPLITS 32  // fine-grain j-splits: 4096 CTAs of 4 tiles -> near-ideal makespan

// ---------------- device scratch (no allocations allowed) ----------------
__device__ float    g_Wh[MDIM * CDIM];
__device__ float    g_x [MDIM * CDIM];
__device__ float    g_t3[MDIM * 64];
__device__ float    g_src[MDIM * NHEADS];
__device__ float    g_dst[MDIM * NHEADS];
__device__ unsigned g_dmax_u[2][NHEADS];
__device__ unsigned g_Abits[MDIM * WPR];
__device__ float    g_pacc[SPLITS][MDIM * CDIM];   // un-normalized partial outputs
__device__ float    g_pz  [SPLITS][MDIM * NHEADS]; // partial softmax denominators

// ---------------- packed f32x2 helpers (FFMA2) ----------------
__device__ __forceinline__ void ffma2(unsigned long long& acc, unsigned long long a,
                                      unsigned long long b) {
    asm("fma.rn.f32x2 %0, %1, %2, %0;" : "+l"(acc) : "l"(a), "l"(b));
}
__device__ __forceinline__ unsigned long long pack2(float x, float y) {
    unsigned long long r;
    asm("mov.b64 %0, {%1, %2};" : "=l"(r) : "f"(x), "f"(y));
    return r;
}
__device__ __forceinline__ float2 unpack2(unsigned long long v) {
    float2 f;
    asm("mov.b64 {%0, %1}, %2;" : "=f"(f.x), "=f"(f.y) : "l"(v));
    return f;
}

// monotone float<->uint key for atomicMax over signed floats
__device__ __forceinline__ unsigned fkey(float f) {
    unsigned b = __float_as_uint(f);
    return (b & 0x80000000u) ? ~b : (b | 0x80000000u);
}
__device__ __forceinline__ float fdec(unsigned k) {
    return (k & 0x80000000u) ? __uint_as_float(k & 0x7fffffffu) : __uint_as_float(~k);
}

// cp.async helpers
__device__ __forceinline__ unsigned smem_u32(const void* p) {
    unsigned a;
    asm("{ .reg .u64 t; cvta.to.shared.u64 t, %1; cvt.u32.u64 %0, t; }" : "=r"(a) : "l"(p));
    return a;
}
__device__ __forceinline__ void cp_async16(unsigned saddr, const void* gptr) {
    asm volatile("cp.async.ca.shared.global [%0], [%1], 16;" :: "r"(saddr), "l"(gptr));
}
__device__ __forceinline__ void cp_async4(unsigned saddr, const void* gptr) {
    asm volatile("cp.async.ca.shared.global [%0], [%1], 4;" :: "r"(saddr), "l"(gptr));
}
__device__ __forceinline__ void cp_commit() {
    asm volatile("cp.async.commit_group;");
}
__device__ __forceinline__ void cp_wait_all() {
    asm volatile("cp.async.wait_group 0;");
}

// ---------------- adjacency -> bitmask pack (also zeroes dmax keys) ----------
__global__ void pack_kernel(const int* __restrict__ A) {
    int idx = blockIdx.x * 256 + threadIdx.x;        // over 16.7M elements
    if (blockIdx.x == 0 && threadIdx.x < 2 * NHEADS)
        ((unsigned*)g_dmax_u)[threadIdx.x] = 0;      // below every real key
    unsigned b = __ballot_sync(0xffffffffu, A[idx] == 1);
    if ((idx & 31) == 0) g_Abits[idx >> 5] = b;
}

// ---------------- generic GEMM: C[M][N] = A[M][K] @ W[N][K]^T + bias ----
__global__ void gemm_kernel(const float* __restrict__ A, const float* __restrict__ W,
                            const float* __restrict__ bias, float* __restrict__ C,
                            int M, int N, int K) {
    __shared__ float As[16][68];
    __shared__ float Ws[16][68];
    const int tid = threadIdx.x;
    const int tx = tid & 15, ty = tid >> 4;
    const int i0 = blockIdx.y * 64, n0 = blockIdx.x * 64;
    const int lr = tid >> 2, lk = (tid & 3) * 4;

    unsigned long long acc2[4][2] = {};
    for (int k0 = 0; k0 < K; k0 += 16) {
        float4 av = *(const float4*)(A + (size_t)(i0 + lr) * K + k0 + lk);
        As[lk + 0][lr] = av.x; As[lk + 1][lr] = av.y;
        As[lk + 2][lr] = av.z; As[lk + 3][lr] = av.w;
        float4 wv = make_float4(0.f, 0.f, 0.f, 0.f);
        if (n0 + lr < N) wv = *(const float4*)(W + (size_t)(n0 + lr) * K + k0 + lk);
        Ws[lk + 0][lr] = wv.x; Ws[lk + 1][lr] = wv.y;
        Ws[lk + 2][lr] = wv.z; Ws[lk + 3][lr] = wv.w;
        __syncthreads();
#pragma unroll
        for (int kk = 0; kk < 16; kk++) {
            float4 a4 = *(const float4*)&As[kk][ty * 4];
            float4 w4 = *(const float4*)&Ws[kk][tx * 4];
            unsigned long long wp0 = pack2(w4.x, w4.y);
            unsigned long long wp1 = pack2(w4.z, w4.w);
            unsigned long long aa;
            aa = pack2(a4.x, a4.x); ffma2(acc2[0][0], aa, wp0); ffma2(acc2[0][1], aa, wp1);
            aa = pack2(a4.y, a4.y); ffma2(acc2[1][0], aa, wp0); ffma2(acc2[1][1], aa, wp1);
            aa = pack2(a4.z, a4.z); ffma2(acc2[2][0], aa, wp0); ffma2(acc2[2][1], aa, wp1);
            aa = pack2(a4.w, a4.w); ffma2(acc2[3][0], aa, wp0); ffma2(acc2[3][1], aa, wp1);
        }
        __syncthreads();
    }
#pragma unroll
    for (int u = 0; u < 4; u++) {
        int row = i0 + ty * 4 + u;
        float2 p0 = unpack2(acc2[u][0]);
        float2 p1 = unpack2(acc2[u][1]);
        float vals[4] = {p0.x, p0.y, p1.x, p1.y};
#pragma unroll
        for (int v = 0; v < 4; v++) {
            int col = n0 + tx * 4 + v;
            if (col < N) C[(size_t)row * N + col] = vals[v] + bias[col];
        }
    }
}

// ---------------- src/dst scores + fused per-head dst max ----------------
__global__ void srcdst_kernel(const float* __restrict__ Wh, const float* __restrict__ a,
                              unsigned* __restrict__ dmax_u) {
    int idx = blockIdx.x * blockDim.x + threadIdx.x;   // 16384 threads
    int m = idx >> 2, h = idx & 3;
    const float4* w  = (const float4*)(Wh + (size_t)m * CDIM + h * 64);
    const float4* as = (const float4*)(a + h * 128);
    const float4* ad = (const float4*)(a + h * 128 + 64);
    float s = 0.f, d = 0.f;
#pragma unroll
    for (int q = 0; q < 16; q++) {
        float4 wv = w[q], av = as[q], dv = ad[q];
        s += wv.x * av.x + wv.y * av.y + wv.z * av.z + wv.w * av.w;
        d += wv.x * dv.x + wv.y * dv.y + wv.z * dv.z + wv.w * dv.w;
    }
    g_src[idx] = s;
    g_dst[idx] = d;
    float mx = d;
    mx = fmaxf(mx, __shfl_xor_sync(0xffffffffu, mx, 4));
    mx = fmaxf(mx, __shfl_xor_sync(0xffffffffu, mx, 8));
    mx = fmaxf(mx, __shfl_xor_sync(0xffffffffu, mx, 16));
    if ((threadIdx.x & 31) < 4) atomicMax(&dmax_u[threadIdx.x & 3], fkey(mx));
}

// ---------------- fused masked-softmax attention, fine split over j ----------
// blockIdx.x: row tile (32 rows). blockIdx.y: j-split (4 tiles each).
// 2 barriers/tile; next tile's dst/abits prefetched (cp.async) during phase B;
// Wh tile ldgsts latency hidden under phase A.
#define ATTN_SMEM ((32 * 256 + 32 * 128 + 2 * 128) * 4 + 2 * 32 * 4)
#define TILES_PER_SPLIT (MDIM / 32 / SPLITS)
#define L2E 1.4426950408889634f

__global__ __launch_bounds__(256, 4)
void attn_kernel(const float* __restrict__ Wh, const unsigned* __restrict__ dmax_u) {
    extern __shared__ float smem[];
    float* wh_sh  = smem;                       // 32 x 256
    float* e_sh   = smem + 32 * 256;            // 32 x 128  [jj][h*32+ii]
    float* dst_sh = e_sh + 32 * 128;            // double-buffered [buf][h][jj]
    unsigned* abits = (unsigned*)(dst_sh + 256);// double-buffered [buf][32]

    const int tid = threadIdx.x;
    const int i0 = blockIdx.x * 32;
    const int sp = blockIdx.y;
    const int og = tid & 63;
    const int grp = tid >> 6;
    const int h = og >> 4;
    const int task = tid >> 1, half = tid & 1;
    const int aii = task & 31, ahh = task >> 5;
    const int lrow = tid >> 3, lf = tid & 7;

    unsigned long long acc2[4][4] = {};  // [col c][row pair rp]

    float z = 0.f;
    float srcv = g_src[(i0 + aii) * 4 + ahh];
    float tmax = srcv + fdec(dmax_u[ahh]);
    float Mi = fmaxf(tmax, 0.01f * tmax);
    float nMiL = -Mi * L2E;              // folded into exp2 argument

    const float4* Wh4 = (const float4*)Wh;
    const unsigned wh_sh_base = smem_u32(wh_sh) + (unsigned)(lrow * 256) * 4u;
    // per-thread prefetch smem addresses (dst: thread<128 handles (r=tid>>2,h=tid&3))
    const unsigned dst_sh_addr = smem_u32(dst_sh) + (unsigned)((tid & 3) * 32 + (tid >> 2)) * 4u;
    const unsigned abits_addr  = smem_u32(abits) + (unsigned)tid * 4u;

    const int jt0 = sp * TILES_PER_SPLIT;

    // prologue: prefetch dst/abits for first tile into buffer 0
    if (tid < 128) cp_async4(dst_sh_addr, &g_dst[(jt0 * 32 + (tid >> 2)) * 4 + (tid & 3)]);
    if (tid < 32)  cp_async4(abits_addr, &g_Abits[(size_t)(i0 + tid) * WPR + jt0]);
    cp_commit();

#pragma unroll
    for (int t = 0; t < TILES_PER_SPLIT; t++) {
        const int jt = jt0 + t;
        const int j0 = jt * 32;
        const int buf = t & 1;
        cp_wait_all();     // dst/abits(t) landed
        __syncthreads();   // prev phase B done; prefetched data visible CTA-wide
        // async-stage Wh tile (latency hides under phase A)
#pragma unroll
        for (int k2 = 0; k2 < 8; k2++)
            cp_async16(wh_sh_base + (unsigned)(lf + 8 * k2) * 16u,
                       Wh4 + (size_t)(j0 + lrow) * 64 + lf + 8 * k2);
        cp_commit();
        // phase A: 16 masked exp scores per thread (vectorized dst loads)
        {
            unsigned bits = abits[buf * 32 + aii] >> (half * 16);
            const float4* dbase = (const float4*)(dst_sh + buf * 128 + ahh * 32 + half * 16);
            float* ebase = e_sh + ahh * 32 + aii + half * 16 * 128;
#pragma unroll
            for (int q4 = 0; q4 < 4; q4++) {
                float4 d4 = dbase[q4];
                float dd[4] = {d4.x, d4.y, d4.z, d4.w};
#pragma unroll
                for (int tt = 0; tt < 4; tt++) {
                    int q = q4 * 4 + tt;
                    float s = srcv + dd[tt];
                    s = fmaxf(s, 0.01f * s);
                    float e = ((bits >> q) & 1u) ? exp2f(fmaf(s, L2E, nMiL)) : 0.f;
                    ebase[q * 128] = e;
                    z += e;
                }
            }
        }
        cp_wait_all();     // Wh(t) landed
        __syncthreads();   // e_sh + wh_sh visible
        // prefetch dst/abits for tile t+1 into the other buffer (hidden under B)
        if (t + 1 < TILES_PER_SPLIT) {
            const int nj0 = (jt + 1) * 32;
            const unsigned nb = (unsigned)((t + 1) & 1);
            if (tid < 128) cp_async4(dst_sh_addr + nb * 512u,
                                     &g_dst[(nj0 + (tid >> 2)) * 4 + (tid & 3)]);
            if (tid < 32)  cp_async4(abits_addr + nb * 128u,
                                     &g_Abits[(size_t)(i0 + tid) * WPR + jt + 1]);
        }
        cp_commit();
        // phase B: acc += e * Wh via packed FFMA2
#pragma unroll 4
        for (int jj = 0; jj < 32; jj++) {
            float4 w = ((const float4*)(wh_sh + jj * 256))[og];
            const ulonglong2* ep = (const ulonglong2*)(e_sh + jj * 128 + h * 32 + grp * 8);
            ulonglong2 ea = ep[0];
            ulonglong2 eb = ep[1];
            unsigned long long ww;
            ww = pack2(w.x, w.x);
            ffma2(acc2[0][0], ww, ea.x); ffma2(acc2[0][1], ww, ea.y);
            ffma2(acc2[0][2], ww, eb.x); ffma2(acc2[0][3], ww, eb.y);
            ww = pack2(w.y, w.y);
            ffma2(acc2[1][0], ww, ea.x); ffma2(acc2[1][1], ww, ea.y);
            ffma2(acc2[1][2], ww, eb.x); ffma2(acc2[1][3], ww, eb.y);
            ww = pack2(w.z, w.z);
            ffma2(acc2[2][0], ww, ea.x); ffma2(acc2[2][1], ww, ea.y);
            ffma2(acc2[2][2], ww, eb.x); ffma2(acc2[2][3], ww, eb.y);
            ww = pack2(w.w, w.w);
            ffma2(acc2[3][0], ww, ea.x); ffma2(acc2[3][1], ww, ea.y);
            ffma2(acc2[3][2], ww, eb.x); ffma2(acc2[3][3], ww, eb.y);
        }
    }
    // publish partial Z (pair-combined) and un-normalized partial acc
    z += __shfl_xor_sync(0xffffffffu, z, 1);
    if (half == 0) g_pz[sp][(i0 + aii) * 4 + ahh] = z;
#pragma unroll
    for (int rp = 0; rp < 4; rp++) {
        int r0 = grp * 8 + 2 * rp, r1 = r0 + 1;
        float2 c0 = unpack2(acc2[0][rp]);
        float2 c1 = unpack2(acc2[1][rp]);
        float2 c2 = unpack2(acc2[2][rp]);
        float2 c3 = unpack2(acc2[3][rp]);
        ((float4*)g_pacc[sp])[(size_t)(i0 + r0) * 64 + og] = make_float4(c0.x, c1.x, c2.x, c3.x);
        ((float4*)g_pacc[sp])[(size_t)(i0 + r1) * 64 + og] = make_float4(c0.y, c1.y, c2.y, c3.y);
    }
}

// ---------------- combine split partials: out = sum(acc) / sum(z) ----------
__global__ void reduce_kernel(float* __restrict__ xout) {
    int idx = blockIdx.x * 256 + threadIdx.x;   // over 4096*64 float4 groups
    int i = idx >> 6, og = idx & 63, h = og >> 4;
    float4 s = make_float4(0.f, 0.f, 0.f, 0.f);
    float z = 0.f;
#pragma unroll 8
    for (int sp = 0; sp < SPLITS; sp++) {
        float4 p = ((const float4*)g_pacc[sp])[idx];
        s.x += p.x; s.y += p.y; s.z += p.z; s.w += p.w;
        z += g_pz[sp][i * 4 + h];
    }
    float inv = 1.0f / z;
    s.x *= inv; s.y *= inv; s.z *= inv; s.w *= inv;
    ((float4*)xout)[idx] = s;
}

// ---------------- launch ----------------
extern "C" void kernel_launch(void* const* d_in, const int* in_sizes, int n_in,
                              void* d_out, int out_size) {
    const float* h    = (const float*)d_in[0];
    const int*   A    = (const int*)  d_in[1];
    const float* W1_w = (const float*)d_in[2];
    const float* W1_b = (const float*)d_in[3];
    const float* a1   = (const float*)d_in[4];
    const float* W3_w = (const float*)d_in[5];
    const float* W3_b = (const float*)d_in[6];
    const float* W2_w = (const float*)d_in[7];
    const float* W2_b = (const float*)d_in[8];
    const float* a2   = (const float*)d_in[9];
    const float* FL_w = (const float*)d_in[10];
    const float* FL_b = (const float*)d_in[11];

    float* out_x   = (float*)d_out;                         // x: (1,4096,256)
    float* out_cls = out_x + (size_t)MDIM * CDIM;           // out: (1,4096,40)

    void* p;
    cudaGetSymbolAddress(&p, g_Wh); float* Wh = (float*)p;
    cudaGetSymbolAddress(&p, g_x);  float* x1 = (float*)p;
    cudaGetSymbolAddress(&p, g_t3); float* t3 = (float*)p;
    cudaGetSymbolAddress(&p, g_dmax_u); unsigned* dmax0 = (unsigned*)p;
    unsigned* dmax1 = dmax0 + NHEADS;

    cudaFuncSetAttribute(attn_kernel, cudaFuncAttributeMaxDynamicSharedMemorySize, ATTN_SMEM);

    pack_kernel<<<(MDIM * MDIM) / 256, 256>>>(A);

    // block 1
    gemm_kernel<<<dim3(4, 64), 256>>>(h, W1_w, W1_b, Wh, MDIM, 256, 512);
    srcdst_kernel<<<64, 256>>>(Wh, a1, dmax0);
    attn_kernel<<<dim3(128, SPLITS), 256, ATTN_SMEM>>>(Wh, dmax0);
    reduce_kernel<<<(MDIM * 64) / 256, 256>>>(x1);
    // middle projection
    gemm_kernel<<<dim3(1, 64), 256>>>(x1, W3_w, W3_b, t3, MDIM, 64, 256);
    // block 2
    gemm_kernel<<<dim3(4, 64), 256>>>(t3, W2_w, W2_b, Wh, MDIM, 256, 64);
    srcdst_kernel<<<64, 256>>>(Wh, a2, dmax1);
    attn_kernel<<<dim3(128, SPLITS), 256, ATTN_SMEM>>>(Wh, dmax1);
    reduce_kernel<<<(MDIM * 64) / 256, 256>>>(out_x);
    // classifier head
    gemm_kernel<<<dim3(1, 64), 256>>>(out_x, FL_w, FL_b, out_cls, MDIM, 40, 256);
}

// round 10
// speedup vs baseline: 1.7055x; 1.0208x over previous
#include <cuda_runtime.h>

#define MDIM 4096
#define CDIM 256   // HEADS*OUT_F
#define NHEADS 4
#define WPR 128    // bitmask words per row (4096/32)
#define SPLITS 32  // fine-grain j-splits: 4096 CTAs of 4 tiles -> near-ideal makespan

// ---------------- device scratch (no allocations allowed) ----------------
__device__ float    g_Wh[MDIM * CDIM];
__device__ float    g_x [MDIM * CDIM];
__device__ float    g_t3[MDIM * 64];
__device__ float    g_src[MDIM * NHEADS];
__device__ float    g_dst[MDIM * NHEADS];
__device__ unsigned g_dmax_u[2][NHEADS];
__device__ unsigned g_Abits[MDIM * WPR];
__device__ float    g_pacc[SPLITS][MDIM * CDIM];   // un-normalized partial outputs
__device__ float    g_pz  [SPLITS][MDIM * NHEADS]; // partial softmax denominators

// ---------------- packed f32x2 helpers (FFMA2) ----------------
__device__ __forceinline__ void ffma2(unsigned long long& acc, unsigned long long a,
                                      unsigned long long b) {
    asm("fma.rn.f32x2 %0, %1, %2, %0;" : "+l"(acc) : "l"(a), "l"(b));
}
__device__ __forceinline__ unsigned long long pack2(float x, float y) {
    unsigned long long r;
    asm("mov.b64 %0, {%1, %2};" : "=l"(r) : "f"(x), "f"(y));
    return r;
}
__device__ __forceinline__ float2 unpack2(unsigned long long v) {
    float2 f;
    asm("mov.b64 {%0, %1}, %2;" : "=f"(f.x), "=f"(f.y) : "l"(v));
    return f;
}

// monotone float<->uint key for atomicMax over signed floats
__device__ __forceinline__ unsigned fkey(float f) {
    unsigned b = __float_as_uint(f);
    return (b & 0x80000000u) ? ~b : (b | 0x80000000u);
}
__device__ __forceinline__ float fdec(unsigned k) {
    return (k & 0x80000000u) ? __uint_as_float(k & 0x7fffffffu) : __uint_as_float(~k);
}

// cp.async helpers
__device__ __forceinline__ unsigned smem_u32(const void* p) {
    unsigned a;
    asm("{ .reg .u64 t; cvta.to.shared.u64 t, %1; cvt.u32.u64 %0, t; }" : "=r"(a) : "l"(p));
    return a;
}
__device__ __forceinline__ void cp_async16(unsigned saddr, const void* gptr) {
    asm volatile("cp.async.ca.shared.global [%0], [%1], 16;" :: "r"(saddr), "l"(gptr));
}
__device__ __forceinline__ void cp_async4(unsigned saddr, const void* gptr) {
    asm volatile("cp.async.ca.shared.global [%0], [%1], 4;" :: "r"(saddr), "l"(gptr));
}
__device__ __forceinline__ void cp_commit() {
    asm volatile("cp.async.commit_group;");
}
__device__ __forceinline__ void cp_wait_all() {
    asm volatile("cp.async.wait_group 0;");
}

// ---------------- adjacency -> bitmask pack (also zeroes dmax keys) ----------
__global__ void pack_kernel(const int* __restrict__ A) {
    int idx = blockIdx.x * 256 + threadIdx.x;        // over 16.7M elements
    if (blockIdx.x == 0 && threadIdx.x < 2 * NHEADS)
        ((unsigned*)g_dmax_u)[threadIdx.x] = 0;      // below every real key
    unsigned b = __ballot_sync(0xffffffffu, A[idx] == 1);
    if ((idx & 31) == 0) g_Abits[idx >> 5] = b;
}

// ---------------- generic GEMM: C[M][N] = A[M][K] @ W[N][K]^T + bias ----
__global__ void gemm_kernel(const float* __restrict__ A, const float* __restrict__ W,
                            const float* __restrict__ bias, float* __restrict__ C,
                            int M, int N, int K) {
    __shared__ float As[16][68];
    __shared__ float Ws[16][68];
    const int tid = threadIdx.x;
    const int tx = tid & 15, ty = tid >> 4;
    const int i0 = blockIdx.y * 64, n0 = blockIdx.x * 64;
    const int lr = tid >> 2, lk = (tid & 3) * 4;

    unsigned long long acc2[4][2] = {};
    for (int k0 = 0; k0 < K; k0 += 16) {
        float4 av = *(const float4*)(A + (size_t)(i0 + lr) * K + k0 + lk);
        As[lk + 0][lr] = av.x; As[lk + 1][lr] = av.y;
        As[lk + 2][lr] = av.z; As[lk + 3][lr] = av.w;
        float4 wv = make_float4(0.f, 0.f, 0.f, 0.f);
        if (n0 + lr < N) wv = *(const float4*)(W + (size_t)(n0 + lr) * K + k0 + lk);
        Ws[lk + 0][lr] = wv.x; Ws[lk + 1][lr] = wv.y;
        Ws[lk + 2][lr] = wv.z; Ws[lk + 3][lr] = wv.w;
        __syncthreads();
#pragma unroll
        for (int kk = 0; kk < 16; kk++) {
            float4 a4 = *(const float4*)&As[kk][ty * 4];
            float4 w4 = *(const float4*)&Ws[kk][tx * 4];
            unsigned long long wp0 = pack2(w4.x, w4.y);
            unsigned long long wp1 = pack2(w4.z, w4.w);
            unsigned long long aa;
            aa = pack2(a4.x, a4.x); ffma2(acc2[0][0], aa, wp0); ffma2(acc2[0][1], aa, wp1);
            aa = pack2(a4.y, a4.y); ffma2(acc2[1][0], aa, wp0); ffma2(acc2[1][1], aa, wp1);
            aa = pack2(a4.z, a4.z); ffma2(acc2[2][0], aa, wp0); ffma2(acc2[2][1], aa, wp1);
            aa = pack2(a4.w, a4.w); ffma2(acc2[3][0], aa, wp0); ffma2(acc2[3][1], aa, wp1);
        }
        __syncthreads();
    }
#pragma unroll
    for (int u = 0; u < 4; u++) {
        int row = i0 + ty * 4 + u;
        float2 p0 = unpack2(acc2[u][0]);
        float2 p1 = unpack2(acc2[u][1]);
        float vals[4] = {p0.x, p0.y, p1.x, p1.y};
#pragma unroll
        for (int v = 0; v < 4; v++) {
            int col = n0 + tx * 4 + v;
            if (col < N) C[(size_t)row * N + col] = vals[v] + bias[col];
        }
    }
}

// ---------------- src/dst scores + fused per-head dst max ----------------
__global__ void srcdst_kernel(const float* __restrict__ Wh, const float* __restrict__ a,
                              unsigned* __restrict__ dmax_u) {
    int idx = blockIdx.x * blockDim.x + threadIdx.x;   // 16384 threads
    int m = idx >> 2, h = idx & 3;
    const float4* w  = (const float4*)(Wh + (size_t)m * CDIM + h * 64);
    const float4* as = (const float4*)(a + h * 128);
    const float4* ad = (const float4*)(a + h * 128 + 64);
    float s = 0.f, d = 0.f;
#pragma unroll
    for (int q = 0; q < 16; q++) {
        float4 wv = w[q], av = as[q], dv = ad[q];
        s += wv.x * av.x + wv.y * av.y + wv.z * av.z + wv.w * av.w;
        d += wv.x * dv.x + wv.y * dv.y + wv.z * dv.z + wv.w * dv.w;
    }
    g_src[idx] = s;
    g_dst[idx] = d;
    float mx = d;
    mx = fmaxf(mx, __shfl_xor_sync(0xffffffffu, mx, 4));
    mx = fmaxf(mx, __shfl_xor_sync(0xffffffffu, mx, 8));
    mx = fmaxf(mx, __shfl_xor_sync(0xffffffffu, mx, 16));
    if ((threadIdx.x & 31) < 4) atomicMax(&dmax_u[threadIdx.x & 3], fkey(mx));
}

// ---------------- fused masked-softmax attention, fine split over j ----------
// Crossbar-optimized mappings:
//  phase A: warp = 32 rows of one (head, jj-half) -> contiguous 128B STS (1 wf)
//           and warp-uniform dst loads (broadcast).
//  phase B: warp = 64 cols x 16 rows -> wh loads dedup to 2 wf/jj (lanes 16-31
//           mirror lanes 0-15), e loads contiguous 64B (1 wf).
#define ATTN_SMEM ((32 * 256 + 32 * 128 + 2 * 128) * 4 + 2 * 32 * 4)
#define TILES_PER_SPLIT (MDIM / 32 / SPLITS)
#define L2E 1.4426950408889634f

__global__ __launch_bounds__(256, 4)
void attn_kernel(const float* __restrict__ Wh, const unsigned* __restrict__ dmax_u) {
    extern __shared__ float smem[];
    float* wh_sh  = smem;                       // 32 x 256
    float* e_sh   = smem + 32 * 256;            // 32 x 128  [jj][h*32+ii]
    float* dst_sh = e_sh + 32 * 128;            // double-buffered [buf][h*32+jj]; reused for z
    unsigned* abits = (unsigned*)(dst_sh + 256);// double-buffered [buf][32]

    const int tid = threadIdx.x;
    const int i0 = blockIdx.x * 32;
    const int sp = blockIdx.y;
    // phase-B identity: warp covers 64 cols (one head) x 16 rows
    const int wid = tid >> 5, lane = tid & 31;
    const int hB = wid & 3;                       // head of this warp's columns
    const int cg = hB * 16 + (lane & 15);         // float4 col group 0..63
    const int rg = ((wid >> 2) << 1) + (lane >> 4); // row group 0..3 (8 rows)
    // phase-A identity: warp = 32 rows of one (head, jj-half)
    const int task = tid & 127, half = tid >> 7;
    const int aii = task & 31, ahh = task >> 5;   // aii == lane, ahh warp-uniform
    const int lrow = tid >> 3, lf = tid & 7;

    unsigned long long acc2[4][4] = {};  // [col c][row pair rp]

    float z = 0.f;
    float srcv = g_src[(i0 + aii) * 4 + ahh];
    float tmax = srcv + fdec(dmax_u[ahh]);
    float Mi = fmaxf(tmax, 0.01f * tmax);
    float nMiL = -Mi * L2E;              // folded into exp2 argument

    const float4* Wh4 = (const float4*)Wh;
    const unsigned wh_sh_base = smem_u32(wh_sh) + (unsigned)(lrow * 256) * 4u;
    // per-thread prefetch smem addresses (dst: thread<128 handles (r=tid>>2,h=tid&3))
    const unsigned dst_sh_addr = smem_u32(dst_sh) + (unsigned)((tid & 3) * 32 + (tid >> 2)) * 4u;
    const unsigned abits_addr  = smem_u32(abits) + (unsigned)tid * 4u;

    const int jt0 = sp * TILES_PER_SPLIT;

    // prologue: prefetch dst/abits for first tile into buffer 0
    if (tid < 128) cp_async4(dst_sh_addr, &g_dst[(jt0 * 32 + (tid >> 2)) * 4 + (tid & 3)]);
    if (tid < 32)  cp_async4(abits_addr, &g_Abits[(size_t)(i0 + tid) * WPR + jt0]);
    cp_commit();

#pragma unroll
    for (int t = 0; t < TILES_PER_SPLIT; t++) {
        const int jt = jt0 + t;
        const int j0 = jt * 32;
        const int buf = t & 1;
        cp_wait_all();     // dst/abits(t) landed
        __syncthreads();   // prev phase B done; prefetched data visible CTA-wide
        // async-stage Wh tile (latency hides under phase A)
#pragma unroll
        for (int k2 = 0; k2 < 8; k2++)
            cp_async16(wh_sh_base + (unsigned)(lf + 8 * k2) * 16u,
                       Wh4 + (size_t)(j0 + lrow) * 64 + lf + 8 * k2);
        cp_commit();
        // phase A: 16 masked exp scores per thread; warp-contiguous e_sh stores
        {
            unsigned bits = abits[buf * 32 + aii] >> (half * 16);
            const float4* dbase = (const float4*)(dst_sh + buf * 128 + ahh * 32 + half * 16);
            float* ebase = e_sh + ahh * 32 + aii + half * 16 * 128;
#pragma unroll
            for (int q4 = 0; q4 < 4; q4++) {
                float4 d4 = dbase[q4];       // warp-uniform (broadcast)
                float dd[4] = {d4.x, d4.y, d4.z, d4.w};
#pragma unroll
                for (int tt = 0; tt < 4; tt++) {
                    int q = q4 * 4 + tt;
                    float s = srcv + dd[tt];
                    s = fmaxf(s, 0.01f * s);
                    float e = ((bits >> q) & 1u) ? exp2f(fmaf(s, L2E, nMiL)) : 0.f;
                    ebase[q * 128] = e;      // 32 consecutive floats per warp: 1 wf
                    z += e;
                }
            }
        }
        cp_wait_all();     // Wh(t) landed
        __syncthreads();   // e_sh + wh_sh visible
        // prefetch dst/abits for tile t+1 into the other buffer (hidden under B)
        if (t + 1 < TILES_PER_SPLIT) {
            const int nj0 = (jt + 1) * 32;
            const unsigned nb = (unsigned)((t + 1) & 1);
            if (tid < 128) cp_async4(dst_sh_addr + nb * 512u,
                                     &g_dst[(nj0 + (tid >> 2)) * 4 + (tid & 3)]);
            if (tid < 32)  cp_async4(abits_addr + nb * 128u,
                                     &g_Abits[(size_t)(i0 + tid) * WPR + jt + 1]);
        }
        cp_commit();
        // phase B: acc += e * Wh via packed FFMA2 (wh loads dedup across half-warps)
#pragma unroll 4
        for (int jj = 0; jj < 32; jj++) {
            float4 w = ((const float4*)(wh_sh + jj * 256))[cg];
            const ulonglong2* ep = (const ulonglong2*)(e_sh + jj * 128 + hB * 32 + rg * 8);
            ulonglong2 ea = ep[0];
            ulonglong2 eb = ep[1];
            unsigned long long ww;
            ww = pack2(w.x, w.x);
            ffma2(acc2[0][0], ww, ea.x); ffma2(acc2[0][1], ww, ea.y);
            ffma2(acc2[0][2], ww, eb.x); ffma2(acc2[0][3], ww, eb.y);
            ww = pack2(w.y, w.y);
            ffma2(acc2[1][0], ww, ea.x); ffma2(acc2[1][1], ww, ea.y);
            ffma2(acc2[1][2], ww, eb.x); ffma2(acc2[1][3], ww, eb.y);
            ww = pack2(w.z, w.z);
            ffma2(acc2[2][0], ww, ea.x); ffma2(acc2[2][1], ww, ea.y);
            ffma2(acc2[2][2], ww, eb.x); ffma2(acc2[2][3], ww, eb.y);
            ww = pack2(w.w, w.w);
            ffma2(acc2[3][0], ww, ea.x); ffma2(acc2[3][1], ww, ea.y);
            ffma2(acc2[3][2], ww, eb.x); ffma2(acc2[3][3], ww, eb.y);
        }
    }
    // combine z across jj-halves via smem staging (dst_sh free after last phase A)
    dst_sh[tid] = z;
    __syncthreads();
    if (tid < 128)
        g_pz[sp][(i0 + (tid & 31)) * 4 + (tid >> 5)] = dst_sh[tid] + dst_sh[tid + 128];
    // un-normalized partial acc
#pragma unroll
    for (int rp = 0; rp < 4; rp++) {
        int r0 = rg * 8 + 2 * rp, r1 = r0 + 1;
        float2 c0 = unpack2(acc2[0][rp]);
        float2 c1 = unpack2(acc2[1][rp]);
        float2 c2 = unpack2(acc2[2][rp]);
        float2 c3 = unpack2(acc2[3][rp]);
        ((float4*)g_pacc[sp])[(size_t)(i0 + r0) * 64 + cg] = make_float4(c0.x, c1.x, c2.x, c3.x);
        ((float4*)g_pacc[sp])[(size_t)(i0 + r1) * 64 + cg] = make_float4(c0.y, c1.y, c2.y, c3.y);
    }
}

// ---------------- combine split partials: out = sum(acc) / sum(z) ----------
__global__ void reduce_kernel(float* __restrict__ xout) {
    int idx = blockIdx.x * 256 + threadIdx.x;   // over 4096*64 float4 groups
    int i = idx >> 6, og = idx & 63, h = og >> 4;
    float4 s = make_float4(0.f, 0.f, 0.f, 0.f);
    float z = 0.f;
#pragma unroll 8
    for (int sp = 0; sp < SPLITS; sp++) {
        float4 p = ((const float4*)g_pacc[sp])[idx];
        s.x += p.x; s.y += p.y; s.z += p.z; s.w += p.w;
        z += g_pz[sp][i * 4 + h];
    }
    float inv = 1.0f / z;
    s.x *= inv; s.y *= inv; s.z *= inv; s.w *= inv;
    ((float4*)xout)[idx] = s;
}

// ---------------- launch ----------------
extern "C" void kernel_launch(void* const* d_in, const int* in_sizes, int n_in,
                              void* d_out, int out_size) {
    const float* h    = (const float*)d_in[0];
    const int*   A    = (const int*)  d_in[1];
    const float* W1_w = (const float*)d_in[2];
    const float* W1_b = (const float*)d_in[3];
    const float* a1   = (const float*)d_in[4];
    const float* W3_w = (const float*)d_in[5];
    const float* W3_b = (const float*)d_in[6];
    const float* W2_w = (const float*)d_in[7];
    const float* W2_b = (const float*)d_in[8];
    const float* a2   = (const float*)d_in[9];
    const float* FL_w = (const float*)d_in[10];
    const float* FL_b = (const float*)d_in[11];

    float* out_x   = (float*)d_out;                         // x: (1,4096,256)
    float* out_cls = out_x + (size_t)MDIM * CDIM;           // out: (1,4096,40)

    void* p;
    cudaGetSymbolAddress(&p, g_Wh); float* Wh = (float*)p;
    cudaGetSymbolAddress(&p, g_x);  float* x1 = (float*)p;
    cudaGetSymbolAddress(&p, g_t3); float* t3 = (float*)p;
    cudaGetSymbolAddress(&p, g_dmax_u); unsigned* dmax0 = (unsigned*)p;
    unsigned* dmax1 = dmax0 + NHEADS;

    cudaFuncSetAttribute(attn_kernel, cudaFuncAttributeMaxDynamicSharedMemorySize, ATTN_SMEM);

    pack_kernel<<<(MDIM * MDIM) / 256, 256>>>(A);

    // block 1
    gemm_kernel<<<dim3(4, 64), 256>>>(h, W1_w, W1_b, Wh, MDIM, 256, 512);
    srcdst_kernel<<<64, 256>>>(Wh, a1, dmax0);
    attn_kernel<<<dim3(128, SPLITS), 256, ATTN_SMEM>>>(Wh, dmax0);
    reduce_kernel<<<(MDIM * 64) / 256, 256>>>(x1);
    // middle projection
    gemm_kernel<<<dim3(1, 64), 256>>>(x1, W3_w, W3_b, t3, MDIM, 64, 256);
    // block 2
    gemm_kernel<<<dim3(4, 64), 256>>>(t3, W2_w, W2_b, Wh, MDIM, 256, 64);
    srcdst_kernel<<<64, 256>>>(Wh, a2, dmax1);
    attn_kernel<<<dim3(128, SPLITS), 256, ATTN_SMEM>>>(Wh, dmax1);
    reduce_kernel<<<(MDIM * 64) / 256, 256>>>(out_x);
    // classifier head
    gemm_kernel<<<dim3(1, 64), 256>>>(out_x, FL_w, FL_b, out_cls, MDIM, 40, 256);
}